// round 10
// baseline (speedup 1.0000x reference)
#include <cuda_runtime.h>
#include <cstdint>

#define NXX 64
#define DTT 1e-4f

__device__ __forceinline__ float tanh_approx(float x) {
    float t;
    asm("tanh.approx.f32 %0, %1;" : "=f"(t) : "f"(x));
    return t;
}
__device__ __forceinline__ uint64_t pack2(float lo, float hi) {
    uint64_t r;
    asm("mov.b64 %0, {%1, %2};" : "=l"(r) : "f"(lo), "f"(hi));
    return r;
}
__device__ __forceinline__ void unpack2(uint64_t v, float& lo, float& hi) {
    asm("mov.b64 {%0, %1}, %2;" : "=f"(lo), "=f"(hi) : "l"(v));
}
__device__ __forceinline__ uint64_t fma2(uint64_t a, uint64_t b, uint64_t c) {
    uint64_t d;
    asm("fma.rn.f32x2 %0, %1, %2, %3;" : "=l"(d) : "l"(a), "l"(b), "l"(c));
    return d;
}
__device__ __forceinline__ uint64_t add2(uint64_t a, uint64_t b) {
    uint64_t d;
    asm("add.rn.f32x2 %0, %1, %2;" : "=l"(d) : "l"(a), "l"(b));
    return d;
}

// 256 threads: 4 lanes per grid point (p = tid>>2, s = tid&3) => 8 warps,
// 2 warps per SMSP. Per-warp stream is only ~48 instructions (fma2-packed),
// so the second warp fills the first's latency stalls (LDS 29, tanh 16,
// shfl 26, barrier) instead of competing for issue. MUFU floor unchanged
// (16 tanh warp-ops/SMSP -> 128 cyc/step).
// Lane s owns 8 hidden units (s<2 -> layer1 else layer2; (s&1) picks half),
// processed as 4 f32x2 PAIRS.
// Stencil folded into weights: z = Wp*up + Wm*um + zb,
//   Wp = 31.5*Wg + 3969*Wl, Wm = -31.5*Wg + 3969*Wl, Wuc = Wu - 7938*Wl
// (f64 folds at init; boundary points: Wp=Wm=0, Wuc=Wu).
// State DUPLICATED as float2 (u,u), loaded as one LDS.64 directly into the
// register pair fma.rn.f32x2 consumes. Per step: LDS first, zb/cb shadow in
// the LDS latency window, MLP, 2-shfl reduce, store, one barrier.
// Head fully folded: Cq = gamma*DT*wc; un = uc + DT*core + gamma*DT*bc + P.
__global__ __launch_bounds__(256, 1) void scct_kernel(
    const float* __restrict__ u0,  const float* __restrict__ w1,
    const float* __restrict__ b1,  const float* __restrict__ w2,
    const float* __restrict__ b2,  const float* __restrict__ wc,
    const float* __restrict__ bc,  const float* __restrict__ gamma_p,
    const int*   __restrict__ nt_p, float* __restrict__ out)
{
    __shared__ float2 ub2[2][NXX];

    const int tid = threadIdx.x;
    const int p = tid >> 2;   // grid point 0..63
    const int s = tid & 3;    // hidden-unit sub-slot

    const float* wsel = (s < 2) ? w1 : w2;
    const float* bsel = (s < 2) ? b1 : b2;
    const int jbase = (s & 1) * 8;

    const float gmm = *gamma_p;
    const float gdt = gmm * DTT;
    const bool interior = (p > 0) && (p < NXX - 1);

    uint64_t Wp2[4], Wm2[4], Wuc2[4], Bq2[4], Cq2[4];
#pragma unroll
    for (int j = 0; j < 4; j++) {
        float pl[2], ml[2], ul[2], bl[2], cl[2];
#pragma unroll
        for (int h = 0; h < 2; h++) {
            int q = jbase + 2 * j + h;          // row within selected layer
            int m = s * 8 + 2 * j + h;          // index into wc (0..31)
            double Wu = (double)wsel[q * 3 + 0];
            double Wg = (double)wsel[q * 3 + 1];
            double Wl = (double)wsel[q * 3 + 2];
            if (interior) {
                pl[h] = (float)( 31.5 * Wg + 3969.0 * Wl);
                ml[h] = (float)(-31.5 * Wg + 3969.0 * Wl);
                ul[h] = (float)(Wu - 7938.0 * Wl);
            } else {
                pl[h] = 0.0f;
                ml[h] = 0.0f;
                ul[h] = (float)Wu;
            }
            bl[h] = bsel[q];
            cl[h] = gdt * wc[m];
        }
        Wp2[j]  = pack2(pl[0], pl[1]);
        Wm2[j]  = pack2(ml[0], ml[1]);
        Wuc2[j] = pack2(ul[0], ul[1]);
        Bq2[j]  = pack2(bl[0], bl[1]);
        Cq2[j]  = pack2(cl[0], cl[1]);
    }
    const float Kc = gdt * (*bc);
    const int Nt = *nt_p;

    if (tid < NXX) {
        float v = u0[tid];
        ub2[0][tid] = make_float2(v, v);
    }
    __syncthreads();

    const float INVDX2 = 3969.0f;  // 63^2

    const int pm = (p == 0) ? 0 : p - 1;
    const int pp = (p == NXX - 1) ? NXX - 1 : p + 1;

    float uc = ub2[0][p].x;
    int cur = 0;

    for (int it = 0; it < Nt; ++it) {
        // ---- chain head: LDS.64 issues FIRST (29-cyc latency) ----
        const uint64_t um2 = *reinterpret_cast<const uint64_t*>(&ub2[cur][pm]);
        const uint64_t up2 = *reinterpret_cast<const uint64_t*>(&ub2[cur][pp]);

        // ---- shadow: register-only, fills the LDS latency window ----
        uint64_t zb2[4];
        {
            const uint64_t uc2 = pack2(uc, uc);
#pragma unroll
            for (int j = 0; j < 4; j++) zb2[j] = fma2(Wuc2[j], uc2, Bq2[j]);
        }
        const float cb = fmaf(0.5f, uc, -(uc * uc * uc));   // 0.5u - u^3

        // ---- MLP: 4 f32x2 pairs, 2 independent acc chains ----
        uint64_t A0 = 0ull, A1 = 0ull;
#pragma unroll
        for (int j = 0; j < 4; j++) {
            uint64_t z2 = fma2(Wp2[j], up2, fma2(Wm2[j], um2, zb2[j]));
            float zl, zh;
            unpack2(z2, zl, zh);
            uint64_t t2 = pack2(tanh_approx(zl), tanh_approx(zh));
            if (j & 1) A1 = fma2(Cq2[j], t2, A1);
            else       A0 = fma2(Cq2[j], t2, A0);
        }
        float al, ah;
        unpack2(add2(A0, A1), al, ah);
        float P = al + ah;
        P += __shfl_xor_sync(0xffffffffu, P, 1);
        P += __shfl_xor_sync(0xffffffffu, P, 2);   // full head sum in all 4 lanes

        // core/base overlap the shfl chain
        float um, up, dumm;
        unpack2(um2, um, dumm);
        unpack2(up2, up, dumm);
        const float lx   = ((up - 2.0f * uc) + um) * INVDX2;
        const float core = fmaf(0.8f, lx, cb);
        const float base = fmaf(DTT, core, uc) + Kc;

        float un = base + P;
        un = interior ? un : 0.0f;

        if (s == 0) ub2[cur ^ 1][p] = make_float2(un, un);
        __syncthreads();

        uc = un;
        cur ^= 1;
    }

    // ---- epilogue: u, phi2, entropy of 64-bin histogram of |u|/max ----
    if (tid < NXX) out[tid] = ub2[cur][tid].x;

    if (tid == 0) {
        float s2 = 0.0f, vmax = 0.0f;
        for (int i = 0; i < NXX; i++) {
            float u = ub2[cur][i].x;
            s2 += u * u;
            vmax = fmaxf(vmax, fabsf(u));
        }
        float phi2 = s2 * (1.0f / 64.0f);

        int hist[64];
#pragma unroll
        for (int i = 0; i < 64; i++) hist[i] = 0;
        float denom = fmaxf(vmax, 1e-12f);
        for (int i = 0; i < NXX; i++) {
            float vn = fabsf(ub2[cur][i].x) / denom;   // IEEE div, matches ref
            int b = (int)(vn * 64.0f);
            if (b > 63) b = 63;
            hist[b]++;
        }
        float H = 0.0f;
        for (int i = 0; i < 64; i++) {
            if (hist[i] > 0) {
                float pb = (float)hist[i] * (1.0f / 64.0f);
                H -= pb * logf(pb);
            }
        }
        if (vmax < 1e-12f) H = 0.0f;
        out[64] = phi2;
        out[65] = H;
    }
}

extern "C" void kernel_launch(void* const* d_in, const int* in_sizes, int n_in,
                              void* d_out, int out_size) {
    (void)in_sizes; (void)n_in; (void)out_size;
    scct_kernel<<<1, 256>>>(
        (const float*)d_in[0],  // u0
        (const float*)d_in[1],  // w1
        (const float*)d_in[2],  // b1
        (const float*)d_in[3],  // w2
        (const float*)d_in[4],  // b2
        (const float*)d_in[5],  // wc
        (const float*)d_in[6],  // bc
        (const float*)d_in[7],  // gamma
        (const int*)  d_in[8],  // Nt
        (float*)d_out);
}

// round 11
// speedup vs baseline: 1.1266x; 1.1266x over previous
#include <cuda_runtime.h>
#include <cstdint>

#define NXX 64
#define DTT 1e-4f

__device__ __forceinline__ float tanh_approx(float x) {
    float t;
    asm("tanh.approx.f32 %0, %1;" : "=f"(t) : "f"(x));
    return t;
}
__device__ __forceinline__ uint64_t pack2(float lo, float hi) {
    uint64_t r;
    asm("mov.b64 %0, {%1, %2};" : "=l"(r) : "f"(lo), "f"(hi));
    return r;
}
__device__ __forceinline__ void unpack2(uint64_t v, float& lo, float& hi) {
    asm("mov.b64 {%0, %1}, %2;" : "=f"(lo), "=f"(hi) : "l"(v));
}
__device__ __forceinline__ uint64_t fma2(uint64_t a, uint64_t b, uint64_t c) {
    uint64_t d;
    asm("fma.rn.f32x2 %0, %1, %2, %3;" : "=l"(d) : "l"(a), "l"(b), "l"(c));
    return d;
}
__device__ __forceinline__ uint64_t add2(uint64_t a, uint64_t b) {
    uint64_t d;
    asm("add.rn.f32x2 %0, %1, %2;" : "=l"(d) : "l"(a), "l"(b));
    return d;
}

// 128 threads: 2 lanes per grid point (p = tid>>1, s = tid&1); lane s owns
// one full 16-unit layer as 8 f32x2 pairs (FFMA2; tanh.approx on MUFU).
//
// SHFL-FREE REDUCE: un = base + P0 + P1 with base = uc + DT*core + gdt*bc
// computable by BOTH lanes before any reduction. Producer stores the RAW
// triplet {base, P0, P1} per point (float4 slot: s0 stores (base,P0) as
// .xy, s1 stores P1 as .z) and arrives at the barrier immediately — the
// shfl(26)+adds leave the pre-barrier critical path. Consumers load each
// neighbor triplet with one LDS.128 and reconstruct u = (base+P0)+P1
// (2 adds in the LDS shadow). Reconstruction is bitwise-identical in every
// lane (same inputs, same op order), so the dynamics stay consistent.
//
// Boundary (p=0,63): Cq=0 and base forced 0 at those points => un == 0
// with no select on the store path.
//
// Stencil folded into weights (f64 at init): z = Wuc*uc + Wp*up + Wm*um + B,
//   Wp = 31.5*Wg + 3969*Wl, Wm = -31.5*Wg + 3969*Wl, Wuc = Wu - 7938*Wl.
// Head folded: Cq = gamma*DT*wc, Kc = gamma*DT*bc.
__global__ __launch_bounds__(128, 1) void scct_kernel(
    const float* __restrict__ u0,  const float* __restrict__ w1,
    const float* __restrict__ b1,  const float* __restrict__ w2,
    const float* __restrict__ b2,  const float* __restrict__ wc,
    const float* __restrict__ bc,  const float* __restrict__ gamma_p,
    const int*   __restrict__ nt_p, float* __restrict__ out)
{
    __shared__ float4 ub4[2][NXX];   // {base, P0, P1, unused} per point

    const int tid = threadIdx.x;
    const int p = tid >> 1;   // grid point 0..63
    const int s = tid & 1;    // layer select

    const float* wsel = s ? w2 : w1;
    const float* bsel = s ? b2 : b1;

    const float gmm = *gamma_p;
    const float gdt = gmm * DTT;
    const bool interior = (p > 0) && (p < NXX - 1);

    uint64_t Wp2[8], Wm2[8], Wuc2[8], Bq2[8], Cq2[8];
#pragma unroll
    for (int j = 0; j < 8; j++) {
        float pl[2], ml[2], ul[2], bl[2], cl[2];
#pragma unroll
        for (int h = 0; h < 2; h++) {
            int q = 2 * j + h;
            double Wu = (double)wsel[q * 3 + 0];
            double Wg = (double)wsel[q * 3 + 1];
            double Wl = (double)wsel[q * 3 + 2];
            if (interior) {
                pl[h] = (float)( 31.5 * Wg + 3969.0 * Wl);
                ml[h] = (float)(-31.5 * Wg + 3969.0 * Wl);
                ul[h] = (float)(Wu - 7938.0 * Wl);
                cl[h] = gdt * wc[s * 16 + q];
            } else {
                pl[h] = 0.0f;
                ml[h] = 0.0f;
                ul[h] = (float)Wu;
                cl[h] = 0.0f;             // boundary: P contributions vanish
            }
            bl[h] = bsel[q];
        }
        Wp2[j]  = pack2(pl[0], pl[1]);
        Wm2[j]  = pack2(ml[0], ml[1]);
        Wuc2[j] = pack2(ul[0], ul[1]);
        Bq2[j]  = pack2(bl[0], bl[1]);
        Cq2[j]  = pack2(cl[0], cl[1]);
    }
    const float Kc = gdt * (*bc);
    const int Nt = *nt_p;

    if (tid < NXX) {
        float v = u0[tid];
        ub4[0][tid] = make_float4(v, 0.0f, 0.0f, 0.0f);  // triplet form of u0
    }
    __syncthreads();

    const float INVDX2 = 3969.0f;  // 63^2

    const int pm = (p == 0) ? 0 : p - 1;
    const int pp = (p == NXX - 1) ? NXX - 1 : p + 1;

    int cur = 0;

    for (int it = 0; it < Nt; ++it) {
        // ---- chain head: 3 pipelined LDS.128 (neighbors + own point) ----
        const float4 m4 = ub4[cur][pm];
        const float4 p4 = ub4[cur][pp];
        const float4 c4 = ub4[cur][p];

        // reconstruct u values (2 adds each; identical in every lane)
        const float um = (m4.x + m4.y) + m4.z;
        const float up = (p4.x + p4.y) + p4.z;
        const float uc = (c4.x + c4.y) + c4.z;

        const uint64_t um2 = pack2(um, um);
        const uint64_t up2 = pack2(up, up);
        const uint64_t uc2 = pack2(uc, uc);

        // ---- MLP: 8 f32x2 pairs, 3-term z, 2 independent acc chains ----
        uint64_t A0 = 0ull, A1 = 0ull;
#pragma unroll
        for (int j = 0; j < 8; j++) {
            uint64_t z2 = fma2(Wuc2[j], uc2,
                          fma2(Wp2[j], up2,
                          fma2(Wm2[j], um2, Bq2[j])));
            float zl, zh;
            unpack2(z2, zl, zh);
            uint64_t t2 = pack2(tanh_approx(zl), tanh_approx(zh));
            if (j & 1) A1 = fma2(Cq2[j], t2, A1);
            else       A0 = fma2(Cq2[j], t2, A0);
        }
        float al, ah;
        unpack2(add2(A0, A1), al, ah);
        const float Ppart = al + ah;           // this lane's partial head sum

        // base (both lanes; overlaps the MUFU stream)
        const float lx   = ((up - 2.0f * uc) + um) * INVDX2;
        const float cb   = fmaf(0.5f, uc, -(uc * uc * uc));
        const float core = fmaf(0.8f, lx, cb);
        const float base = interior ? (fmaf(DTT, core, uc) + Kc) : 0.0f;

        // ---- store raw triplet, NO reduce before the barrier ----
        float4* dst = &ub4[cur ^ 1][p];
        if (s == 0) {
            *reinterpret_cast<float2*>(dst) = make_float2(base, Ppart); // .xy
        } else {
            dst->z = Ppart;                                             // .z
        }
        __syncthreads();

        cur ^= 1;
    }

    // ---- epilogue: reconstruct u, then phi2 + histogram entropy ----
    __shared__ float uf[NXX];
    if (tid < NXX) {
        float4 v = ub4[cur][tid];
        float u = (v.x + v.y) + v.z;
        uf[tid] = u;
        out[tid] = u;
    }
    __syncthreads();

    if (tid == 0) {
        float s2 = 0.0f, vmax = 0.0f;
        for (int i = 0; i < NXX; i++) {
            float u = uf[i];
            s2 += u * u;
            vmax = fmaxf(vmax, fabsf(u));
        }
        float phi2 = s2 * (1.0f / 64.0f);

        int hist[64];
#pragma unroll
        for (int i = 0; i < 64; i++) hist[i] = 0;
        float denom = fmaxf(vmax, 1e-12f);
        for (int i = 0; i < NXX; i++) {
            float vn = fabsf(uf[i]) / denom;   // IEEE div, matches ref
            int b = (int)(vn * 64.0f);
            if (b > 63) b = 63;
            hist[b]++;
        }
        float H = 0.0f;
        for (int i = 0; i < 64; i++) {
            if (hist[i] > 0) {
                float pb = (float)hist[i] * (1.0f / 64.0f);
                H -= pb * logf(pb);
            }
        }
        if (vmax < 1e-12f) H = 0.0f;
        out[64] = phi2;
        out[65] = H;
    }
}

extern "C" void kernel_launch(void* const* d_in, const int* in_sizes, int n_in,
                              void* d_out, int out_size) {
    (void)in_sizes; (void)n_in; (void)out_size;
    scct_kernel<<<1, 128>>>(
        (const float*)d_in[0],  // u0
        (const float*)d_in[1],  // w1
        (const float*)d_in[2],  // b1
        (const float*)d_in[3],  // w2
        (const float*)d_in[4],  // b2
        (const float*)d_in[5],  // wc
        (const float*)d_in[6],  // bc
        (const float*)d_in[7],  // gamma
        (const int*)  d_in[8],  // Nt
        (float*)d_out);
}